// round 1
// baseline (speedup 1.0000x reference)
#include <cuda_runtime.h>
#include <cuda_bf16.h>
#include <cstdint>

// Residual quantization: N=65536 rows, D=512, K=1024 codes/level, L=4 levels.
// Fused persistent-tile kernel: each block owns 64 rows, keeps the residual in
// SMEM across all 4 levels, streams the codebook through SMEM, and does an
// exact-fp32 argmin that mimics the reference's rounding:
//   d = (r_sq + c_sq) - 2*dot   (fp32, r_sq added so dists land on ulp(512) grid)
//   argmin = first index of min  (u64 key = dist_bits<<32 | k)

#define NROWS   65536
#define DDIM    512
#define KCB     1024
#define LLEV    4
#define ROWS    64        // rows per block
#define TPB     256
#define KTILE   64        // k per tile
#define DCHUNK  128       // d per smem chunk of codebook
#define RSTRIDE 516       // padded row stride for residual (bank-friendly, 16B-aligned)

__device__ float g_csq[LLEV * KCB];

// ---------------------------------------------------------------------------
// c_sq precompute: one warp per codebook row
// ---------------------------------------------------------------------------
__global__ void csq_kernel(const float* __restrict__ cb) {
    int warp = (blockIdx.x * blockDim.x + threadIdx.x) >> 5;
    int lane = threadIdx.x & 31;
    if (warp >= LLEV * KCB) return;
    const float4* p = (const float4*)(cb + (size_t)warp * DDIM);
    float s = 0.f;
    #pragma unroll
    for (int i = lane; i < DDIM / 4; i += 32) {
        float4 v = p[i];
        s = fmaf(v.x, v.x, s);
        s = fmaf(v.y, v.y, s);
        s = fmaf(v.z, v.z, s);
        s = fmaf(v.w, v.w, s);
    }
    #pragma unroll
    for (int o = 16; o; o >>= 1) s += __shfl_down_sync(0xffffffffu, s, o);
    if (lane == 0) g_csq[warp] = s;
}

// ---------------------------------------------------------------------------
// Main fused RQ kernel
// ---------------------------------------------------------------------------
__global__ void __launch_bounds__(TPB, 1)
rq_kernel(const float* __restrict__ inp, const float* __restrict__ cb,
          float* __restrict__ outq, float* __restrict__ outc, int write_codes)
{
    extern __shared__ float sm[];
    float* Rs    = sm;                         // [64][516]   residual (row-major, padded)
    float* Cs    = Rs + ROWS * RSTRIDE;        // [128][64]   codebook chunk, d-major
    float* csq_s = Cs + DCHUNK * KTILE;        // [1024]      c_sq for current level
    float* rsq_s = csq_s + KCB;                // [64]
    float* part  = rsq_s + ROWS;               // [4][64]
    unsigned long long* rowkey =
        (unsigned long long*)(part + 4 * ROWS);  // [64] (offset is 8B aligned)

    const int t  = threadIdx.x;
    const int n0 = blockIdx.x * ROWS;
    const int tx = t & 7;    // k sub-tile (8 k's per thread)
    const int ty = t >> 3;   // row pair (2 rows per thread)

    // Load residual = inputs (coalesced, conflict-free STS)
    {
        const float4* ip = (const float4*)(inp + (size_t)n0 * DDIM);
        for (int i = t; i < ROWS * (DDIM / 4); i += TPB) {
            int row = i >> 7, dq = i & 127;
            float4 v = ip[(size_t)row * (DDIM / 4) + dq];
            *(float4*)(Rs + row * RSTRIDE + 4 * dq) = v;
        }
    }

    for (int l = 0; l < LLEV; ++l) {
        const float* cbl = cb + (size_t)l * KCB * DDIM;
        __syncthreads();  // residual update of prev level done; rowkey safe to reset

        // c_sq for this level, rowkey reset, r_sq partials
        for (int i = t; i < KCB; i += TPB) csq_s[i] = g_csq[l * KCB + i];
        if (t < ROWS) rowkey[t] = ~0ull;
        {
            int row = t & 63, q = t >> 6;
            const float* rp = Rs + row * RSTRIDE + q * 128;
            float s = 0.f;
            #pragma unroll 8
            for (int d = 0; d < 128; ++d) { float v = rp[d]; s = fmaf(v, v, s); }
            part[q * ROWS + row] = s;
        }
        __syncthreads();
        if (t < ROWS)
            rsq_s[t] = ((part[t] + part[ROWS + t]) + part[2 * ROWS + t]) + part[3 * ROWS + t];
        // (sync before first use is provided by the barrier at top of the d-chunk loop)

        for (int kt = 0; kt < KCB / KTILE; ++kt) {
            const int kbase = kt * KTILE;
            float acc[2][8];
            #pragma unroll
            for (int i = 0; i < 2; ++i)
                #pragma unroll
                for (int j = 0; j < 8; ++j) acc[i][j] = 0.f;

            for (int dc = 0; dc < DDIM; dc += DCHUNK) {
                __syncthreads();  // prev Cs consumers done / rsq_s visible
                // load Cs[d][k]: k = i&63, dq = i>>6 -> conflict-free STS
                for (int i = t; i < KTILE * (DCHUNK / 4); i += TPB) {
                    int k = i & 63, dq = i >> 6;  // dq in [0,32)
                    float4 v = ((const float4*)(cbl + (size_t)(kbase + k) * DDIM + dc))[dq];
                    float* dst = Cs + (4 * dq) * KTILE + k;
                    dst[0]         = v.x;
                    dst[KTILE]     = v.y;
                    dst[2 * KTILE] = v.z;
                    dst[3 * KTILE] = v.w;
                }
                __syncthreads();

                const float* rp0 = Rs + (2 * ty) * RSTRIDE + dc;
                const float* rp1 = rp0 + RSTRIDE;
                const float* cp  = Cs + 8 * tx;
                #pragma unroll 8
                for (int dd = 0; dd < DCHUNK; ++dd) {
                    float r0 = rp0[dd];
                    float r1 = rp1[dd];
                    float4 ca = *(const float4*)(cp + dd * KTILE);
                    float4 cc = *(const float4*)(cp + dd * KTILE + 4);
                    acc[0][0] = fmaf(r0, ca.x, acc[0][0]);
                    acc[0][1] = fmaf(r0, ca.y, acc[0][1]);
                    acc[0][2] = fmaf(r0, ca.z, acc[0][2]);
                    acc[0][3] = fmaf(r0, ca.w, acc[0][3]);
                    acc[0][4] = fmaf(r0, cc.x, acc[0][4]);
                    acc[0][5] = fmaf(r0, cc.y, acc[0][5]);
                    acc[0][6] = fmaf(r0, cc.z, acc[0][6]);
                    acc[0][7] = fmaf(r0, cc.w, acc[0][7]);
                    acc[1][0] = fmaf(r1, ca.x, acc[1][0]);
                    acc[1][1] = fmaf(r1, ca.y, acc[1][1]);
                    acc[1][2] = fmaf(r1, ca.z, acc[1][2]);
                    acc[1][3] = fmaf(r1, ca.w, acc[1][3]);
                    acc[1][4] = fmaf(r1, cc.x, acc[1][4]);
                    acc[1][5] = fmaf(r1, cc.y, acc[1][5]);
                    acc[1][6] = fmaf(r1, cc.z, acc[1][6]);
                    acc[1][7] = fmaf(r1, cc.w, acc[1][7]);
                }
            }

            // scores + argmin keys (dist_bits<<32 | k  => min key == first-min-index)
            unsigned long long best0 = ~0ull, best1 = ~0ull;
            float rsq0 = rsq_s[2 * ty];
            float rsq1 = rsq_s[2 * ty + 1];
            #pragma unroll
            for (int j = 0; j < 8; ++j) {
                int k = kbase + 8 * tx + j;
                float cq = csq_s[k];
                float d0 = (rsq0 + cq) - 2.0f * acc[0][j];
                float d1 = (rsq1 + cq) - 2.0f * acc[1][j];
                unsigned long long k0 =
                    ((unsigned long long)__float_as_uint(d0) << 32) | (unsigned)k;
                unsigned long long k1 =
                    ((unsigned long long)__float_as_uint(d1) << 32) | (unsigned)k;
                if (k0 < best0) best0 = k0;
                if (k1 < best1) best1 = k1;
            }
            // reduce across the 8 tx lanes of each row
            #pragma unroll
            for (int o = 4; o; o >>= 1) {
                unsigned long long b0 = __shfl_down_sync(0xffffffffu, best0, o);
                unsigned long long b1 = __shfl_down_sync(0xffffffffu, best1, o);
                if (b0 < best0) best0 = b0;
                if (b1 < best1) best1 = b1;
            }
            if (tx == 0) {
                atomicMin(&rowkey[2 * ty], best0);
                atomicMin(&rowkey[2 * ty + 1], best1);
            }
        }
        __syncthreads();

        // gather chosen codewords; update quant (gmem) and residual (smem)
        for (int i = t; i < ROWS * (DDIM / 4); i += TPB) {
            int row = i >> 7, dq = i & 127;
            unsigned idx = (unsigned)(rowkey[row] & 0xffffffffu);
            float4 e = ((const float4*)(cbl + (size_t)idx * DDIM))[dq];
            float4* qp = (float4*)(outq + (size_t)(n0 + row) * DDIM) + dq;
            float4 q;
            if (l == 0) {
                q = e;  // quant = 0 + e0
            } else {
                q = *qp;
                q.x += e.x; q.y += e.y; q.z += e.z; q.w += e.w;
            }
            *qp = q;
            float* rp = Rs + row * RSTRIDE + 4 * dq;
            rp[0] -= e.x; rp[1] -= e.y; rp[2] -= e.z; rp[3] -= e.w;
        }
        if (write_codes && t < ROWS) {
            unsigned idx = (unsigned)(rowkey[t] & 0xffffffffu);
            outc[(size_t)(n0 + t) * LLEV + l] = (float)idx;
        }
    }
}

// ---------------------------------------------------------------------------
extern "C" void kernel_launch(void* const* d_in, const int* in_sizes, int n_in,
                              void* d_out, int out_size) {
    const float* inp = (const float*)d_in[0];
    const float* cb  = (const float*)d_in[1];
    // robust to metadata ordering: inputs is N*D, codebooks is L*K*D
    if (n_in >= 2 && in_sizes[0] == LLEV * KCB * DDIM &&
        in_sizes[1] == NROWS * DDIM) {
        const float* tmp = inp; inp = cb; cb = tmp;
    }

    float* outq = (float*)d_out;
    float* outc = nullptr;
    int write_codes = 0;
    long long quant_elems = (long long)NROWS * DDIM;
    if ((long long)out_size >= quant_elems + (long long)NROWS * LLEV) {
        write_codes = 1;
        outc = outq + quant_elems;
    }

    // c_sq: one warp per (l,k) row
    csq_kernel<<<(LLEV * KCB * 32 + TPB - 1) / TPB, TPB>>>(cb);

    size_t smem_bytes =
        (size_t)(ROWS * RSTRIDE + DCHUNK * KTILE + KCB + ROWS + 4 * ROWS) * sizeof(float)
        + ROWS * sizeof(unsigned long long);
    cudaFuncSetAttribute(rq_kernel, cudaFuncAttributeMaxDynamicSharedMemorySize,
                         (int)smem_bytes);
    rq_kernel<<<NROWS / ROWS, TPB, smem_bytes>>>(inp, cb, outq, outc, write_codes);
}